// round 11
// baseline (speedup 1.0000x reference)
#include <cuda_runtime.h>

// WindowEmbedding forward: out[b, t, k*D + d] = (t-k >= 0) ? in[b, t-k, d] : 0
// B=16, T=2048, D=256, W=7.
// R10: persistent grid (148 SMs x 4 blocks = 592) with grid-stride over the
// 4096 t-tiles. Removes 6.9-wave quantization + per-block dispatch/setup of
// the R9 layout while keeping its proven inner loop (direct float4 loads,
// MLP=8 batch, __stcs streaming stores). Converged model: ~209 MB DRAM at
// ~5.3 TB/s pure-write effective => floor ~39us; this targets the last
// scheduling overhead above that floor.

#define B_DIM 16
#define T_DIM 2048
#define D_DIM 256
#define W_DIM 7

#define D4 (D_DIM / 4)          // 64 float4 per input row
#define SLICE4 (W_DIM * D4)     // 448 float4 per output row
#define TILE_T 8                // t-values per tile
#define NTILES (B_DIM * T_DIM / TILE_T)   // 4096
#define GRID_P (148 * 4)        // persistent grid: one wave

__global__ __launch_bounds__(SLICE4) void window_embed_kernel(
    const float4* __restrict__ in,   // [B, T, 64] float4
    float4* __restrict__ out)        // [B, T, 448] float4
{
    const int tid = threadIdx.x;             // 0..447
    const int k   = tid >> 6;                // shift 0..6
    const int d4  = tid & 63;                // float4 column
    const int koff = -k * D4 + d4;           // src offset relative to bt0*D4

    for (int tile = blockIdx.x; tile < NTILES; tile += GRID_P) {
        const int bt0 = tile * TILE_T;       // b*T + t0, t0 multiple of 8
        const int t0  = bt0 & (T_DIM - 1);

        const float4* src = in  + (bt0 * D4 + koff);   // signed 32-bit offset
        float4*       dst = out + (bt0 * SLICE4 + tid);

        float4 v[TILE_T];

        if (t0 != 0) {
            // Fast path (4080/4096 tiles): t0 >= 8 > k, all sources valid.
            #pragma unroll
            for (int j = 0; j < TILE_T; j++)
                v[j] = src[j * D4];
            #pragma unroll
            for (int j = 0; j < TILE_T; j++)
                __stcs(&dst[j * SLICE4], v[j]);
        } else {
            // t0 == 0: zero-fill where t - k < 0.
            #pragma unroll
            for (int j = 0; j < TILE_T; j++) {
                const int ts = j - k;
                v[j] = (ts >= 0) ? src[j * D4]
                                 : make_float4(0.f, 0.f, 0.f, 0.f);
            }
            #pragma unroll
            for (int j = 0; j < TILE_T; j++)
                __stcs(&dst[j * SLICE4], v[j]);
        }
    }
}

extern "C" void kernel_launch(void* const* d_in, const int* in_sizes, int n_in,
                              void* d_out, int out_size)
{
    const float4* in = (const float4*)d_in[0];
    float4* out = (float4*)d_out;

    dim3 grid(GRID_P);                   // 592 persistent blocks, one wave
    dim3 block(SLICE4);                  // 448
    window_embed_kernel<<<grid, block>>>(in, out);
}

// round 12
// speedup vs baseline: 1.0967x; 1.0967x over previous
#include <cuda_runtime.h>

// WindowEmbedding forward: out[b, t, k*D + d] = (t-k >= 0) ? in[b, t-k, d] : 0
// B=16, T=2048, D=256, W=7.
// R11 = R9 (FINAL). Best measured: kernel 39.55us, DRAM 66.8%, rel_err 0.
// Seven structural variants (direct STG.128 / smem+stcs / smem+plain / TMA
// bulk / STG.256 / persistent grid) all bracket the same ~5.3 TB/s
// pure-write DRAM ceiling on ~209 MB of irreducible traffic (output is a 7x
// expansion by definition). Oversubscribed 4096-block launch beats the
// persistent grid: inter-block overlap is the prefetching. ~39.5us is the
// practical floor; this kernel sits within ~1% of it.

#define B_DIM 16
#define T_DIM 2048
#define D_DIM 256
#define W_DIM 7

#define D4 (D_DIM / 4)          // 64 float4 per input row
#define SLICE4 (W_DIM * D4)     // 448 float4 per output row
#define TILE_T 8                // t-values per thread

__global__ __launch_bounds__(SLICE4) void window_embed_kernel(
    const float4* __restrict__ in,   // [B, T, 64] float4
    float4* __restrict__ out)        // [B, T, 448] float4
{
    const int bt0 = blockIdx.x * TILE_T;     // base (b*T + t0), t0 multiple of 8
    const int t0  = bt0 & (T_DIM - 1);
    const int tid = threadIdx.x;             // 0..447
    const int k   = tid >> 6;                // shift 0..6
    const int d4  = tid & 63;                // float4 column

    // Signed 32-bit offsets: max magnitude ~14.7M, sign-extends correctly
    // for the (rare) bt0 - k < 0 base in block 0.
    const int soff = (bt0 - k) * D4 + d4;    // may be slightly negative
    const int doff = bt0 * SLICE4 + tid;

    const float4* src = in  + soff;          // OOB base only when t0==0, k>0;
    float4*       dst = out + doff;          //   never dereferenced there.

    float4 v[TILE_T];

    if (t0 != 0) {
        // Fast path (4080/4096 blocks): t0 >= 8 > k, all sources valid.
        #pragma unroll
        for (int j = 0; j < TILE_T; j++)
            v[j] = src[j * D4];
        #pragma unroll
        for (int j = 0; j < TILE_T; j++)
            __stcs(&dst[j * SLICE4], v[j]);
    } else {
        // t0 == 0: zero-fill where t - k < 0.
        #pragma unroll
        for (int j = 0; j < TILE_T; j++) {
            const int ts = j - k;
            v[j] = (ts >= 0) ? src[j * D4] : make_float4(0.f, 0.f, 0.f, 0.f);
        }
        #pragma unroll
        for (int j = 0; j < TILE_T; j++)
            __stcs(&dst[j * SLICE4], v[j]);
    }
}

extern "C" void kernel_launch(void* const* d_in, const int* in_sizes, int n_in,
                              void* d_out, int out_size)
{
    const float4* in = (const float4*)d_in[0];
    float4* out = (float4*)d_out;

    dim3 grid(B_DIM * T_DIM / TILE_T);   // 4096
    dim3 block(SLICE4);                  // 448
    window_embed_kernel<<<grid, block>>>(in, out);
}

// round 13
// speedup vs baseline: 1.1095x; 1.0116x over previous
#include <cuda_runtime.h>

// WindowEmbedding forward: out[b, t, k*D + d] = (t-k >= 0) ? in[b, t-k, d] : 0
// B=16, T=2048, D=256, W=7.
// R12: R9/R11 inner structure (best measured, kernel 39.55us) with 2x block
// coarsening: 896 threads cover 2 adjacent 8-t tiles IN PARALLEL (two
// 448-thread slices, no serial loop -- R10's mistake). Halves block count to
// 2048 while keeping threads/SM, per-thread MLP=8, and __stcs streaming
// stores identical. Converged model: ~209 MB irreducible DRAM writes at
// ~5.3 TB/s effective => ~39.5us floor; this probes the last dispatch
// overhead above it.

#define B_DIM 16
#define T_DIM 2048
#define D_DIM 256
#define W_DIM 7

#define D4 (D_DIM / 4)          // 64 float4 per input row
#define SLICE4 (W_DIM * D4)     // 448 float4 per output row
#define TILE_T 8                // t-values per thread
#define SLICES 2                // t-tiles per block (parallel, not serial)
#define NTHREADS (SLICES * SLICE4)   // 896

__global__ __launch_bounds__(NTHREADS) void window_embed_kernel(
    const float4* __restrict__ in,   // [B, T, 64] float4
    float4* __restrict__ out)        // [B, T, 448] float4
{
    const int tid   = threadIdx.x;               // 0..895
    const int slice = tid / SLICE4;              // 0..1: which t-tile
    const int stid  = tid - slice * SLICE4;      // 0..447 within slice
    const int k     = stid >> 6;                 // shift 0..6
    const int d4    = stid & 63;                 // float4 column

    const int bt0 = (blockIdx.x * SLICES + slice) * TILE_T;  // b*T + t0
    const int t0  = bt0 & (T_DIM - 1);

    // Signed 32-bit offsets (max magnitude ~14.7M); sign handles bt0-k<0.
    const float4* src = in  + ((bt0 - k) * D4 + d4);
    float4*       dst = out + (bt0 * SLICE4 + stid);

    float4 v[TILE_T];

    if (t0 != 0) {
        // Fast path: t0 >= 8 > k, all sources valid.
        #pragma unroll
        for (int j = 0; j < TILE_T; j++)
            v[j] = src[j * D4];
        #pragma unroll
        for (int j = 0; j < TILE_T; j++)
            __stcs(&dst[j * SLICE4], v[j]);
    } else {
        // t0 == 0 (16 slices total): zero-fill where t - k < 0.
        #pragma unroll
        for (int j = 0; j < TILE_T; j++) {
            const int ts = j - k;
            v[j] = (ts >= 0) ? src[j * D4] : make_float4(0.f, 0.f, 0.f, 0.f);
        }
        #pragma unroll
        for (int j = 0; j < TILE_T; j++)
            __stcs(&dst[j * SLICE4], v[j]);
    }
}

extern "C" void kernel_launch(void* const* d_in, const int* in_sizes, int n_in,
                              void* d_out, int out_size)
{
    const float4* in = (const float4*)d_in[0];
    float4* out = (float4*)d_out;

    dim3 grid(B_DIM * T_DIM / (TILE_T * SLICES));   // 2048
    dim3 block(NTHREADS);                           // 896
    window_embed_kernel<<<grid, block>>>(in, out);
}